// round 1
// baseline (speedup 1.0000x reference)
#include <cuda_runtime.h>
#include <cstdint>
#include <cstddef>

#define SCALE_F 0.125f

// Scratch (device globals — no allocation allowed)
__device__ float g_q[2 * 256 * 4096];     // [b][o][n], o = head*64+d  -> [bh][d][n]
__device__ float g_k[2 * 256 * 4096];     // same layout
__device__ float g_v[8 * 4096 * 64];      // [bh][m][dv]
__device__ float g_qh[8 * 4096 * 128];    // [bh][n][r], r stride 128 (127 valid)
__device__ float g_qw[8 * 4096 * 128];

// ---------------------------------------------------------------------------
// Kernel 1: QKV projection. qkv[b][o][n] = sum_c x[b][c][n] * w[o][c]
// grid (64 n-tiles, 12 o-tiles, 2 b), 256 threads, 64x64 tile, 4x4 per thread.
// ---------------------------------------------------------------------------
__global__ void __launch_bounds__(256) qkv_kernel(const float* __restrict__ x,
                                                  const float* __restrict__ w) {
    __shared__ float WsT[16 * 68];   // [c][o]
    __shared__ float Xs[16 * 68];    // [c][n]
    const int t = threadIdx.x;
    const int tx = t & 15, ty = t >> 4;
    const int b = blockIdx.z;
    const int o0 = blockIdx.y * 64;
    const int n0 = blockIdx.x * 64;
    const float* xb = x + (size_t)b * 256 * 4096;

    float acc[4][4];
#pragma unroll
    for (int i = 0; i < 4; i++)
#pragma unroll
        for (int j = 0; j < 4; j++) acc[i][j] = 0.f;

    const int wo = t >> 2, wcg = (t & 3) << 2;  // W-load mapping
    for (int c0 = 0; c0 < 256; c0 += 16) {
        __syncthreads();
        // load W tile transposed: WsT[c][o]
        float4 wv = *(const float4*)(w + (size_t)(o0 + wo) * 256 + c0 + wcg);
        WsT[(wcg + 0) * 68 + wo] = wv.x;
        WsT[(wcg + 1) * 68 + wo] = wv.y;
        WsT[(wcg + 2) * 68 + wo] = wv.z;
        WsT[(wcg + 3) * 68 + wo] = wv.w;
        // load X tile natural: Xs[c][n]
        *(float4*)(Xs + ty * 68 + tx * 4) =
            *(const float4*)(xb + (size_t)(c0 + ty) * 4096 + n0 + tx * 4);
        __syncthreads();
#pragma unroll
        for (int c = 0; c < 16; c++) {
            const float4 a4 = *(const float4*)(WsT + c * 68 + ty * 4);
            const float4 b4 = *(const float4*)(Xs + c * 68 + tx * 4);
            const float av[4] = {a4.x, a4.y, a4.z, a4.w};
            const float bv[4] = {b4.x, b4.y, b4.z, b4.w};
#pragma unroll
            for (int ri = 0; ri < 4; ri++)
#pragma unroll
                for (int cj = 0; cj < 4; cj++) acc[ri][cj] += av[ri] * bv[cj];
        }
    }

    const int nbase = n0 + tx * 4;
#pragma unroll
    for (int ri = 0; ri < 4; ri++) {
        int o = o0 + ty * 4 + ri;
        float4 r4 = make_float4(acc[ri][0], acc[ri][1], acc[ri][2], acc[ri][3]);
        if (o < 256) {
            *(float4*)(g_q + ((size_t)b * 256 + o) * 4096 + nbase) = r4;
        } else if (o < 512) {
            *(float4*)(g_k + ((size_t)b * 256 + (o - 256)) * 4096 + nbase) = r4;
        } else {
            int oo = o - 512;
            int bh = b * 4 + (oo >> 6);
            int dv = oo & 63;
#pragma unroll
            for (int cj = 0; cj < 4; cj++)
                g_v[((size_t)bh * 4096 + nbase + cj) * 64 + dv] = acc[ri][cj];
        }
    }
}

// ---------------------------------------------------------------------------
// Kernel 2: rel-pos logits. out[bh][n][r] = sum_d q[bh][d][n] * rel[r][d]
// grid (64 n-tiles, 8 bh, 2 type{height,width}), 256 threads.
// Each thread: 8 n x 4 r. r==127 is zero-filled (never read).
// ---------------------------------------------------------------------------
__global__ void __launch_bounds__(256) rel_kernel(const float* __restrict__ hrel,
                                                  const float* __restrict__ wrel) {
    __shared__ float qs[64 * 64];     // [d][n]
    __shared__ float relT[64 * 128];  // [d][r]
    const int t = threadIdx.x;
    const int bh = blockIdx.y;
    const int n0 = blockIdx.x * 64;
    const float* rel = blockIdx.z ? wrel : hrel;
    float* outb = blockIdx.z ? g_qw : g_qh;

    // load q tile (d-major, coalesced)
    for (int idx = t * 4; idx < 4096; idx += 1024) {
        int d = idx >> 6, nn = idx & 63;
        *(float4*)(qs + d * 64 + nn) =
            *(const float4*)(g_q + ((size_t)bh * 64 + d) * 4096 + n0 + nn);
    }
    // load rel transposed with zero fill at r=127
    {
        int r = t >> 1, half = t & 1;
#pragma unroll
        for (int k = 0; k < 8; k++) {
            int d = half * 32 + k * 4;
            float4 rv = (r < 127) ? *(const float4*)(rel + r * 64 + d)
                                  : make_float4(0.f, 0.f, 0.f, 0.f);
            relT[(d + 0) * 128 + r] = rv.x;
            relT[(d + 1) * 128 + r] = rv.y;
            relT[(d + 2) * 128 + r] = rv.z;
            relT[(d + 3) * 128 + r] = rv.w;
        }
    }
    __syncthreads();

    const int tr = t & 31;   // r group (4 r's)
    const int tn = t >> 5;   // n group (8 n's)
    float acc[8][4];
#pragma unroll
    for (int i = 0; i < 8; i++)
#pragma unroll
        for (int j = 0; j < 4; j++) acc[i][j] = 0.f;

#pragma unroll 8
    for (int d = 0; d < 64; d++) {
        const float4 b4 = *(const float4*)(relT + d * 128 + tr * 4);
        const float4 a0 = *(const float4*)(qs + d * 64 + tn * 8);
        const float4 a1 = *(const float4*)(qs + d * 64 + tn * 8 + 4);
        const float av[8] = {a0.x, a0.y, a0.z, a0.w, a1.x, a1.y, a1.z, a1.w};
        const float bv[4] = {b4.x, b4.y, b4.z, b4.w};
#pragma unroll
        for (int i = 0; i < 8; i++)
#pragma unroll
            for (int j = 0; j < 4; j++) acc[i][j] += av[i] * bv[j];
    }
#pragma unroll
    for (int i = 0; i < 8; i++) {
        *(float4*)(outb + ((size_t)bh * 4096 + n0 + tn * 8 + i) * 128 + tr * 4) =
            make_float4(acc[i][0], acc[i][1], acc[i][2], acc[i][3]);
    }
}

// ---------------------------------------------------------------------------
// Kernel 3: flash attention. grid (64 query blocks, 8 bh), 256 threads.
// Query block qb: queries n = qb*64+i -> (h1=qb, w1=i). Key block j: keys
// m = j*64+w2 -> (h2=j, w2). Bias = QH[n][j-qb+63] (scalar/row/block)
//                          + QW[n][w2-i+63]   (register tile, block-invariant)
// ---------------------------------------------------------------------------
__global__ void __launch_bounds__(256) flash_kernel(float* __restrict__ out) {
    extern __shared__ float sm[];
    float* QsT = sm;            // [d][i]  (pre-scaled by SCALE)
    float* KsT = sm + 4096;     // [d][j]
    float* Vs = sm + 8192;      // [m][dv]
    float* Ps = sm + 12288;     // [i][m]
    float* qhs = sm + 16384;    // [64]

    const int t = threadIdx.x;
    const int tx = t & 15, ty = t >> 4;
    const int bh = blockIdx.y;
    const int qb = blockIdx.x;
    const int n0 = qb * 64;
    const float* qg = g_q + (size_t)bh * 64 * 4096;
    const float* kg = g_k + (size_t)bh * 64 * 4096;
    const float* vg = g_v + (size_t)bh * 4096 * 64;

    // Q tile (scaled)
    for (int idx = t * 4; idx < 4096; idx += 1024) {
        int d = idx >> 6, i = idx & 63;
        float4 v4 = *(const float4*)(qg + (size_t)d * 4096 + n0 + i);
        v4.x *= SCALE_F; v4.y *= SCALE_F; v4.z *= SCALE_F; v4.w *= SCALE_F;
        *(float4*)(QsT + d * 64 + i) = v4;
    }
    // width-rel bias tile (block-invariant)
    float rbias[4][4];
#pragma unroll
    for (int ri = 0; ri < 4; ri++) {
        int i = ty * 4 + ri;
#pragma unroll
        for (int cj = 0; cj < 4; cj++) {
            int w2 = tx * 4 + cj;
            rbias[ri][cj] = g_qw[((size_t)bh * 4096 + n0 + i) * 128 + (w2 - i + 63)];
        }
    }

    float mrow[4] = {-3.0e38f, -3.0e38f, -3.0e38f, -3.0e38f};
    float lrow[4] = {0.f, 0.f, 0.f, 0.f};
    float O[4][4];
#pragma unroll
    for (int ri = 0; ri < 4; ri++)
#pragma unroll
        for (int cj = 0; cj < 4; cj++) O[ri][cj] = 0.f;

    for (int j = 0; j < 64; j++) {
        __syncthreads();  // previous iteration's smem reads done
        for (int idx = t * 4; idx < 4096; idx += 1024) {
            int d = idx >> 6, i = idx & 63;
            *(float4*)(KsT + d * 64 + i) =
                *(const float4*)(kg + (size_t)d * 4096 + j * 64 + i);
            *(float4*)(Vs + d * 64 + i) =
                *(const float4*)(vg + (size_t)(j * 64 + d) * 64 + i);
        }
        if (t < 64)
            qhs[t] = g_qh[((size_t)bh * 4096 + n0 + t) * 128 + (j - qb + 63)];
        __syncthreads();

        // S = scale*QK^T + qh + qw
        float S[4][4];
        float qhr[4];
#pragma unroll
        for (int ri = 0; ri < 4; ri++) qhr[ri] = qhs[ty * 4 + ri];
#pragma unroll
        for (int ri = 0; ri < 4; ri++)
#pragma unroll
            for (int cj = 0; cj < 4; cj++) S[ri][cj] = rbias[ri][cj] + qhr[ri];

#pragma unroll 8
        for (int d = 0; d < 64; d++) {
            const float4 a4 = *(const float4*)(QsT + d * 64 + ty * 4);
            const float4 b4 = *(const float4*)(KsT + d * 64 + tx * 4);
            const float av[4] = {a4.x, a4.y, a4.z, a4.w};
            const float bv[4] = {b4.x, b4.y, b4.z, b4.w};
#pragma unroll
            for (int ri = 0; ri < 4; ri++)
#pragma unroll
                for (int cj = 0; cj < 4; cj++) S[ri][cj] += av[ri] * bv[cj];
        }

        // online softmax (row spread over 16 lanes of same half-warp)
#pragma unroll
        for (int ri = 0; ri < 4; ri++) {
            float mx = fmaxf(fmaxf(S[ri][0], S[ri][1]), fmaxf(S[ri][2], S[ri][3]));
#pragma unroll
            for (int ofs = 8; ofs >= 1; ofs >>= 1)
                mx = fmaxf(mx, __shfl_xor_sync(0xffffffffu, mx, ofs));
            float mnew = fmaxf(mrow[ri], mx);
            float alpha = __expf(mrow[ri] - mnew);
            mrow[ri] = mnew;
            float rs = 0.f;
#pragma unroll
            for (int cj = 0; cj < 4; cj++) {
                S[ri][cj] = __expf(S[ri][cj] - mnew);
                rs += S[ri][cj];
            }
#pragma unroll
            for (int ofs = 8; ofs >= 1; ofs >>= 1)
                rs += __shfl_xor_sync(0xffffffffu, rs, ofs);
            lrow[ri] = lrow[ri] * alpha + rs;
#pragma unroll
            for (int cj = 0; cj < 4; cj++) O[ri][cj] *= alpha;
        }

        // publish P
#pragma unroll
        for (int ri = 0; ri < 4; ri++)
            *(float4*)(Ps + (ty * 4 + ri) * 64 + tx * 4) =
                make_float4(S[ri][0], S[ri][1], S[ri][2], S[ri][3]);
        __syncthreads();

        // O += P @ V
#pragma unroll 2
        for (int m4 = 0; m4 < 64; m4 += 4) {
            float pv[4][4], vv[4][4];
#pragma unroll
            for (int ri = 0; ri < 4; ri++) {
                const float4 p4 = *(const float4*)(Ps + (ty * 4 + ri) * 64 + m4);
                pv[ri][0] = p4.x; pv[ri][1] = p4.y; pv[ri][2] = p4.z; pv[ri][3] = p4.w;
            }
#pragma unroll
            for (int k = 0; k < 4; k++) {
                const float4 v4 = *(const float4*)(Vs + (m4 + k) * 64 + tx * 4);
                vv[k][0] = v4.x; vv[k][1] = v4.y; vv[k][2] = v4.z; vv[k][3] = v4.w;
            }
#pragma unroll
            for (int ri = 0; ri < 4; ri++)
#pragma unroll
                for (int k = 0; k < 4; k++)
#pragma unroll
                    for (int cj = 0; cj < 4; cj++)
                        O[ri][cj] += pv[ri][k] * vv[k][cj];
        }
    }

    // finalize: transpose through smem (reuse Ps as Os[dv][i]) then coalesced write
    __syncthreads();
    float inv_l[4];
#pragma unroll
    for (int ri = 0; ri < 4; ri++) inv_l[ri] = 1.0f / lrow[ri];
    float* Os = Ps;
#pragma unroll
    for (int cj = 0; cj < 4; cj++) {
        int dv = tx * 4 + cj;
        *(float4*)(Os + dv * 64 + ty * 4) =
            make_float4(O[0][cj] * inv_l[0], O[1][cj] * inv_l[1],
                        O[2][cj] * inv_l[2], O[3][cj] * inv_l[3]);
    }
    __syncthreads();

    const int b = bh >> 2, head = bh & 3;
    float* outp = out + ((size_t)(b * 256 + head * 64)) * 4096 + n0;
    const int dv = t >> 2, i0 = (t & 3) * 16;
#pragma unroll
    for (int k = 0; k < 16; k += 4)
        *(float4*)(outp + (size_t)dv * 4096 + i0 + k) =
            *(const float4*)(Os + dv * 64 + i0 + k);
}

// ---------------------------------------------------------------------------
extern "C" void kernel_launch(void* const* d_in, const int* in_sizes, int n_in,
                              void* d_out, int out_size) {
    const float* x = (const float*)d_in[0];
    const float* w = (const float*)d_in[1];
    const float* hrel = (const float*)d_in[2];
    const float* wrel = (const float*)d_in[3];
    float* out = (float*)d_out;

    qkv_kernel<<<dim3(64, 12, 2), 256>>>(x, w);
    rel_kernel<<<dim3(64, 8, 2), 256>>>(hrel, wrel);

    const int flash_smem = (4 * 4096 + 64) * (int)sizeof(float);  // 65792 B
    cudaFuncSetAttribute(flash_kernel, cudaFuncAttributeMaxDynamicSharedMemorySize,
                         flash_smem);
    flash_kernel<<<dim3(64, 8), 256, flash_smem>>>(out);
}

// round 2
// speedup vs baseline: 2.0634x; 2.0634x over previous
#include <cuda_runtime.h>
#include <cstdint>
#include <cstddef>

#define SCALE_F 0.125f

__device__ __forceinline__ float to_tf32(float x) {
    asm("cvt.rna.tf32.f32 %0, %1;" : "=f"(x) : "f"(x));
    return x;
}

__device__ __forceinline__ void mma_tf32(float c[4], uint32_t a0, uint32_t a1,
                                         uint32_t a2, uint32_t a3,
                                         uint32_t b0, uint32_t b1) {
    asm volatile(
        "mma.sync.aligned.m16n8k8.row.col.f32.tf32.tf32.f32 "
        "{%0,%1,%2,%3},{%4,%5,%6,%7},{%8,%9},{%0,%1,%2,%3};\n"
        : "+f"(c[0]), "+f"(c[1]), "+f"(c[2]), "+f"(c[3])
        : "r"(a0), "r"(a1), "r"(a2), "r"(a3), "r"(b0), "r"(b1));
}

// Scratch (device globals — no allocation allowed)
__device__ float g_q[2 * 256 * 4096];     // [bh][d][n]  (tf32-rounded, unscaled)
__device__ float g_k[2 * 256 * 4096];     // [bh][d][n]  (tf32-rounded)
__device__ float g_v[8 * 4096 * 64];      // [bh][m][dv] (tf32-rounded)
__device__ float g_qh[8 * 4096 * 128];    // [bh][n][r], r stride 128 (127 valid)
__device__ float g_qw[8 * 4096 * 128];

// ---------------------------------------------------------------------------
// Kernel 1: QKV projection. qkv[b][o][n] = sum_c x[b][c][n] * w[o][c]
// Output rounded to tf32 so the flash hot loop needs no cvt.
// ---------------------------------------------------------------------------
__global__ void __launch_bounds__(256) qkv_kernel(const float* __restrict__ x,
                                                  const float* __restrict__ w) {
    __shared__ float WsT[16 * 68];   // [c][o]
    __shared__ float Xs[16 * 68];    // [c][n]
    const int t = threadIdx.x;
    const int tx = t & 15, ty = t >> 4;
    const int b = blockIdx.z;
    const int o0 = blockIdx.y * 64;
    const int n0 = blockIdx.x * 64;
    const float* xb = x + (size_t)b * 256 * 4096;

    float acc[4][4];
#pragma unroll
    for (int i = 0; i < 4; i++)
#pragma unroll
        for (int j = 0; j < 4; j++) acc[i][j] = 0.f;

    const int wo = t >> 2, wcg = (t & 3) << 2;
    for (int c0 = 0; c0 < 256; c0 += 16) {
        __syncthreads();
        float4 wv = *(const float4*)(w + (size_t)(o0 + wo) * 256 + c0 + wcg);
        WsT[(wcg + 0) * 68 + wo] = wv.x;
        WsT[(wcg + 1) * 68 + wo] = wv.y;
        WsT[(wcg + 2) * 68 + wo] = wv.z;
        WsT[(wcg + 3) * 68 + wo] = wv.w;
        *(float4*)(Xs + ty * 68 + tx * 4) =
            *(const float4*)(xb + (size_t)(c0 + ty) * 4096 + n0 + tx * 4);
        __syncthreads();
#pragma unroll
        for (int c = 0; c < 16; c++) {
            const float4 a4 = *(const float4*)(WsT + c * 68 + ty * 4);
            const float4 b4 = *(const float4*)(Xs + c * 68 + tx * 4);
            const float av[4] = {a4.x, a4.y, a4.z, a4.w};
            const float bv[4] = {b4.x, b4.y, b4.z, b4.w};
#pragma unroll
            for (int ri = 0; ri < 4; ri++)
#pragma unroll
                for (int cj = 0; cj < 4; cj++) acc[ri][cj] += av[ri] * bv[cj];
        }
    }

    const int nbase = n0 + tx * 4;
#pragma unroll
    for (int ri = 0; ri < 4; ri++) {
        int o = o0 + ty * 4 + ri;
        float4 r4 = make_float4(to_tf32(acc[ri][0]), to_tf32(acc[ri][1]),
                                to_tf32(acc[ri][2]), to_tf32(acc[ri][3]));
        if (o < 256) {
            *(float4*)(g_q + ((size_t)b * 256 + o) * 4096 + nbase) = r4;
        } else if (o < 512) {
            *(float4*)(g_k + ((size_t)b * 256 + (o - 256)) * 4096 + nbase) = r4;
        } else {
            int oo = o - 512;
            int bh = b * 4 + (oo >> 6);
            int dv = oo & 63;
            const float rv[4] = {r4.x, r4.y, r4.z, r4.w};
#pragma unroll
            for (int cj = 0; cj < 4; cj++)
                g_v[((size_t)bh * 4096 + nbase + cj) * 64 + dv] = rv[cj];
        }
    }
}

// ---------------------------------------------------------------------------
// Kernel 2: rel-pos logits. out[bh][n][r] = sum_d q[bh][d][n] * rel[r][d]
// ---------------------------------------------------------------------------
__global__ void __launch_bounds__(256) rel_kernel(const float* __restrict__ hrel,
                                                  const float* __restrict__ wrel) {
    __shared__ float qs[64 * 64];     // [d][n]
    __shared__ float relT[64 * 128];  // [d][r]
    const int t = threadIdx.x;
    const int bh = blockIdx.y;
    const int n0 = blockIdx.x * 64;
    const float* rel = blockIdx.z ? wrel : hrel;
    float* outb = blockIdx.z ? g_qw : g_qh;

    for (int idx = t * 4; idx < 4096; idx += 1024) {
        int d = idx >> 6, nn = idx & 63;
        *(float4*)(qs + d * 64 + nn) =
            *(const float4*)(g_q + ((size_t)bh * 64 + d) * 4096 + n0 + nn);
    }
    {
        int r = t >> 1, half = t & 1;
#pragma unroll
        for (int k = 0; k < 8; k++) {
            int d = half * 32 + k * 4;
            float4 rv = (r < 127) ? *(const float4*)(rel + r * 64 + d)
                                  : make_float4(0.f, 0.f, 0.f, 0.f);
            relT[(d + 0) * 128 + r] = rv.x;
            relT[(d + 1) * 128 + r] = rv.y;
            relT[(d + 2) * 128 + r] = rv.z;
            relT[(d + 3) * 128 + r] = rv.w;
        }
    }
    __syncthreads();

    const int tr = t & 31;
    const int tn = t >> 5;
    float acc[8][4];
#pragma unroll
    for (int i = 0; i < 8; i++)
#pragma unroll
        for (int j = 0; j < 4; j++) acc[i][j] = 0.f;

#pragma unroll 8
    for (int d = 0; d < 64; d++) {
        const float4 b4 = *(const float4*)(relT + d * 128 + tr * 4);
        const float4 a0 = *(const float4*)(qs + d * 64 + tn * 8);
        const float4 a1 = *(const float4*)(qs + d * 64 + tn * 8 + 4);
        const float av[8] = {a0.x, a0.y, a0.z, a0.w, a1.x, a1.y, a1.z, a1.w};
        const float bv[4] = {b4.x, b4.y, b4.z, b4.w};
#pragma unroll
        for (int i = 0; i < 8; i++)
#pragma unroll
            for (int j = 0; j < 4; j++) acc[i][j] += av[i] * bv[j];
    }
#pragma unroll
    for (int i = 0; i < 8; i++) {
        *(float4*)(outb + ((size_t)bh * 4096 + n0 + tn * 8 + i) * 128 + tr * 4) =
            make_float4(acc[i][0], acc[i][1], acc[i][2], acc[i][3]);
    }
}

// ---------------------------------------------------------------------------
// Kernel 3: flash attention, tf32 mma.sync. Br=128, Bc=64, 8 warps.
// Warp w owns query rows [16w, 16w+16) -> softmax fully warp-local.
// ---------------------------------------------------------------------------
#define SK 72   // Ks stride (72 % 32 == 8): B-frag banks 8*qc + lr, conflict-free
#define SV 72
#define SP 76   // Ps stride (76 % 32 == 12): A-frag banks 12*lr + qc, conflict-free
#define SQ 136  // Qs stride (136 % 32 == 8)

__global__ void __launch_bounds__(256, 1) flash_tc_kernel(float* __restrict__ out) {
    extern __shared__ float sm[];
    float* Ks = sm;                      // [d][m]   64*72
    float* Vs = Ks + 64 * SK;            // [m][dv]  64*72
    float* qhs = Vs + 64 * SV;           // [128]
    float* Ps = qhs + 128;               // [i][m] 128*76 ; also Q/O staging 64*136

    const int t = threadIdx.x;
    const int w = t >> 5, lane = t & 31;
    const int lr = lane >> 2, qc = lane & 3;
    const int r0 = w * 16;
    const int bh = blockIdx.y;
    const int qb = blockIdx.x;
    const int n0q = qb * 128;
    const float* qg = g_q + (size_t)bh * 64 * 4096;
    const float* kg = g_k + (size_t)bh * 64 * 4096;
    const float* vg = g_v + (size_t)bh * 4096 * 64;

    // ---- stage Q [d][i] into Ps region (scaled; scale is 2^-3 -> stays tf32)
    float* Qs = Ps;
    for (int idx = t * 4; idx < 8192; idx += 1024) {
        int d = idx >> 7, i = idx & 127;
        float4 v4 = *(const float4*)(qg + (size_t)d * 4096 + n0q + i);
        v4.x *= SCALE_F; v4.y *= SCALE_F; v4.z *= SCALE_F; v4.w *= SCALE_F;
        *(float4*)(Qs + d * SQ + i) = v4;
    }
    __syncthreads();

    // ---- Q A-fragments to registers (8 k-tiles x 4 regs)
    uint32_t qf[8][4];
#pragma unroll
    for (int kt = 0; kt < 8; kt++) {
        qf[kt][0] = __float_as_uint(Qs[(kt * 8 + qc) * SQ + r0 + lr]);
        qf[kt][1] = __float_as_uint(Qs[(kt * 8 + qc) * SQ + r0 + lr + 8]);
        qf[kt][2] = __float_as_uint(Qs[(kt * 8 + qc + 4) * SQ + r0 + lr]);
        qf[kt][3] = __float_as_uint(Qs[(kt * 8 + qc + 4) * SQ + r0 + lr + 8]);
    }

    // ---- width-rel bias, j-invariant, fragment layout (32 regs)
    float qwv[8][4];
    {
        const int i_lo = r0 + lr, i_hi = i_lo + 8;
        const float* qwb = g_qw + ((size_t)bh * 4096 + n0q) * 128;
#pragma unroll
        for (int nt = 0; nt < 8; nt++) {
            int c = nt * 8 + 2 * qc;
            qwv[nt][0] = qwb[(size_t)i_lo * 128 + (c - (i_lo & 63) + 63)];
            qwv[nt][1] = qwb[(size_t)i_lo * 128 + (c + 1 - (i_lo & 63) + 63)];
            qwv[nt][2] = qwb[(size_t)i_hi * 128 + (c - (i_hi & 63) + 63)];
            qwv[nt][3] = qwb[(size_t)i_hi * 128 + (c + 1 - (i_hi & 63) + 63)];
        }
    }

    float m_lo = -3.0e38f, m_hi = -3.0e38f, l_lo = 0.f, l_hi = 0.f;
    float O[8][4];
#pragma unroll
    for (int nt = 0; nt < 8; nt++)
#pragma unroll
        for (int e = 0; e < 4; e++) O[nt][e] = 0.f;

    for (int j = 0; j < 64; j++) {
        __syncthreads();
        // stage K tile [d][m] and V tile [m][dv]
        for (int idx = t * 4; idx < 4096; idx += 1024) {
            int a = idx >> 6, c = idx & 63;
            *(float4*)(Ks + a * SK + c) =
                *(const float4*)(kg + (size_t)a * 4096 + j * 64 + c);
            *(float4*)(Vs + a * SV + c) =
                *(const float4*)(vg + (size_t)(j * 64 + a) * 64 + c);
        }
        if (t < 128) {
            int h1 = qb * 2 + (t >> 6);
            qhs[t] = g_qh[((size_t)bh * 4096 + n0q + t) * 128 + (j - h1 + 63)];
        }
        __syncthreads();

        // ---- S = scale*Q K^T + bias
        float S[8][4];
        const float qh_lo = qhs[r0 + lr], qh_hi = qhs[r0 + lr + 8];
#pragma unroll
        for (int nt = 0; nt < 8; nt++) {
            S[nt][0] = qwv[nt][0] + qh_lo;
            S[nt][1] = qwv[nt][1] + qh_lo;
            S[nt][2] = qwv[nt][2] + qh_hi;
            S[nt][3] = qwv[nt][3] + qh_hi;
        }
#pragma unroll
        for (int kt = 0; kt < 8; kt++) {
#pragma unroll
            for (int nt = 0; nt < 8; nt++) {
                uint32_t b0 = __float_as_uint(Ks[(kt * 8 + qc) * SK + nt * 8 + lr]);
                uint32_t b1 = __float_as_uint(Ks[(kt * 8 + qc + 4) * SK + nt * 8 + lr]);
                mma_tf32(S[nt], qf[kt][0], qf[kt][1], qf[kt][2], qf[kt][3], b0, b1);
            }
        }

        // ---- online softmax (rows warp-local: quad lanes share a row)
        float mx_lo = -3.0e38f, mx_hi = -3.0e38f;
#pragma unroll
        for (int nt = 0; nt < 8; nt++) {
            mx_lo = fmaxf(mx_lo, fmaxf(S[nt][0], S[nt][1]));
            mx_hi = fmaxf(mx_hi, fmaxf(S[nt][2], S[nt][3]));
        }
        mx_lo = fmaxf(mx_lo, __shfl_xor_sync(0xffffffffu, mx_lo, 1));
        mx_lo = fmaxf(mx_lo, __shfl_xor_sync(0xffffffffu, mx_lo, 2));
        mx_hi = fmaxf(mx_hi, __shfl_xor_sync(0xffffffffu, mx_hi, 1));
        mx_hi = fmaxf(mx_hi, __shfl_xor_sync(0xffffffffu, mx_hi, 2));
        const float mnew_lo = fmaxf(m_lo, mx_lo);
        const float mnew_hi = fmaxf(m_hi, mx_hi);
        const float alpha_lo = __expf(m_lo - mnew_lo);
        const float alpha_hi = __expf(m_hi - mnew_hi);
        m_lo = mnew_lo; m_hi = mnew_hi;

        float sum_lo = 0.f, sum_hi = 0.f;
#pragma unroll
        for (int nt = 0; nt < 8; nt++) {
            S[nt][0] = to_tf32(__expf(S[nt][0] - mnew_lo));
            S[nt][1] = to_tf32(__expf(S[nt][1] - mnew_lo));
            S[nt][2] = to_tf32(__expf(S[nt][2] - mnew_hi));
            S[nt][3] = to_tf32(__expf(S[nt][3] - mnew_hi));
            sum_lo += S[nt][0] + S[nt][1];
            sum_hi += S[nt][2] + S[nt][3];
        }
        sum_lo += __shfl_xor_sync(0xffffffffu, sum_lo, 1);
        sum_lo += __shfl_xor_sync(0xffffffffu, sum_lo, 2);
        sum_hi += __shfl_xor_sync(0xffffffffu, sum_hi, 1);
        sum_hi += __shfl_xor_sync(0xffffffffu, sum_hi, 2);
        l_lo = l_lo * alpha_lo + sum_lo;
        l_hi = l_hi * alpha_hi + sum_hi;

        // ---- publish P (warp-private rows), rescale O
#pragma unroll
        for (int nt = 0; nt < 8; nt++) {
            *(float2*)(Ps + (r0 + lr) * SP + nt * 8 + 2 * qc) =
                make_float2(S[nt][0], S[nt][1]);
            *(float2*)(Ps + (r0 + lr + 8) * SP + nt * 8 + 2 * qc) =
                make_float2(S[nt][2], S[nt][3]);
            O[nt][0] *= alpha_lo; O[nt][1] *= alpha_lo;
            O[nt][2] *= alpha_hi; O[nt][3] *= alpha_hi;
        }
        __syncwarp();

        // ---- O += P @ V
#pragma unroll
        for (int kt = 0; kt < 8; kt++) {
            uint32_t pa0 = __float_as_uint(Ps[(r0 + lr) * SP + kt * 8 + qc]);
            uint32_t pa1 = __float_as_uint(Ps[(r0 + lr + 8) * SP + kt * 8 + qc]);
            uint32_t pa2 = __float_as_uint(Ps[(r0 + lr) * SP + kt * 8 + qc + 4]);
            uint32_t pa3 = __float_as_uint(Ps[(r0 + lr + 8) * SP + kt * 8 + qc + 4]);
#pragma unroll
            for (int nt = 0; nt < 8; nt++) {
                uint32_t b0 = __float_as_uint(Vs[(kt * 8 + qc) * SV + nt * 8 + lr]);
                uint32_t b1 = __float_as_uint(Vs[(kt * 8 + qc + 4) * SV + nt * 8 + lr]);
                mma_tf32(O[nt], pa0, pa1, pa2, pa3, b0, b1);
            }
        }
    }

    // ---- epilogue: normalize, transpose through smem, coalesced store
    __syncthreads();
    const float inv_lo = 1.0f / l_lo, inv_hi = 1.0f / l_hi;
    float* Os = Ps;  // [dv][i], stride SQ
#pragma unroll
    for (int nt = 0; nt < 8; nt++) {
        int dv = nt * 8 + 2 * qc;
        Os[(dv + 0) * SQ + r0 + lr] = O[nt][0] * inv_lo;
        Os[(dv + 1) * SQ + r0 + lr] = O[nt][1] * inv_lo;
        Os[(dv + 0) * SQ + r0 + lr + 8] = O[nt][2] * inv_hi;
        Os[(dv + 1) * SQ + r0 + lr + 8] = O[nt][3] * inv_hi;
    }
    __syncthreads();

    const int b = bh >> 2, head = bh & 3;
    float* outp = out + ((size_t)(b * 256 + head * 64)) * 4096 + n0q;
    for (int idx = t * 4; idx < 8192; idx += 1024) {
        int dv = idx >> 7, i = idx & 127;
        *(float4*)(outp + (size_t)dv * 4096 + i) = *(const float4*)(Os + dv * SQ + i);
    }
}

// ---------------------------------------------------------------------------
extern "C" void kernel_launch(void* const* d_in, const int* in_sizes, int n_in,
                              void* d_out, int out_size) {
    const float* x = (const float*)d_in[0];
    const float* w = (const float*)d_in[1];
    const float* hrel = (const float*)d_in[2];
    const float* wrel = (const float*)d_in[3];
    float* out = (float*)d_out;

    qkv_kernel<<<dim3(64, 12, 2), 256>>>(x, w);
    rel_kernel<<<dim3(64, 8, 2), 256>>>(hrel, wrel);

    const int flash_smem = (64 * SK + 64 * SV + 128 + 128 * SP) * (int)sizeof(float);
    cudaFuncSetAttribute(flash_tc_kernel, cudaFuncAttributeMaxDynamicSharedMemorySize,
                         flash_smem);
    flash_tc_kernel<<<dim3(32, 8), 256, flash_smem>>>(out);
}

// round 5
// speedup vs baseline: 4.0724x; 1.9736x over previous
#include <cuda_runtime.h>
#include <cuda_fp16.h>
#include <cstdint>
#include <cstddef>

#define SCALE_F 0.125f

__device__ __forceinline__ uint32_t smem_to_u32(const void* p) {
    uint32_t a;
    asm("{ .reg .u64 t; cvta.to.shared.u64 t, %1; cvt.u32.u64 %0, t; }" : "=r"(a) : "l"(p));
    return a;
}
__device__ __forceinline__ void cp16(uint32_t dst, const void* src) {
    asm volatile("cp.async.cg.shared.global [%0], [%1], 16;" :: "r"(dst), "l"(src) : "memory");
}
#define CP_COMMIT() asm volatile("cp.async.commit_group;" ::: "memory")
template <int N>
__device__ __forceinline__ void cp_wait() {
    asm volatile("cp.async.wait_group %0;" :: "n"(N) : "memory");
}
__device__ __forceinline__ void ldm_x4(uint32_t& r0, uint32_t& r1, uint32_t& r2,
                                       uint32_t& r3, uint32_t addr) {
    asm volatile("ldmatrix.sync.aligned.m8n8.x4.shared.b16 {%0,%1,%2,%3}, [%4];"
                 : "=r"(r0), "=r"(r1), "=r"(r2), "=r"(r3) : "r"(addr));
}
__device__ __forceinline__ void mma_f16(float c[4], uint32_t a0, uint32_t a1,
                                        uint32_t a2, uint32_t a3, uint32_t b0,
                                        uint32_t b1) {
    asm volatile(
        "mma.sync.aligned.m16n8k16.row.col.f32.f16.f16.f32 "
        "{%0,%1,%2,%3},{%4,%5,%6,%7},{%8,%9},{%0,%1,%2,%3};\n"
        : "+f"(c[0]), "+f"(c[1]), "+f"(c[2]), "+f"(c[3])
        : "r"(a0), "r"(a1), "r"(a2), "r"(a3), "r"(b0), "r"(b1));
}
__device__ __forceinline__ uint32_t packh2(float lo, float hi) {
    __half2 h = __floats2half2_rn(lo, hi);
    return *(uint32_t*)&h;
}

// ===================== scratch =====================
__device__ __align__(16) __half g_q16[2 * 4 * 4096 * 64];  // [bh][n][d], pre-scaled x0.125
__device__ __align__(16) __half g_k16[2 * 4 * 4096 * 64];  // [bh][n][d]
__device__ __align__(16) __half g_v16[2 * 4 * 64 * 4096];  // [bh][dv][m]
__device__ float g_qh[8 * 4096 * 128];                     // [bh][n][r]
__device__ float g_qw[8 * 4096 * 128];

// ---------------------------------------------------------------------------
// Kernel 1: QKV projection (fp32 math, fp16 outputs)
// ---------------------------------------------------------------------------
__global__ void __launch_bounds__(256) qkv_kernel(const float* __restrict__ x,
                                                  const float* __restrict__ w) {
    __shared__ float WsT[16 * 68];
    __shared__ float Xs[16 * 68];
    const int t = threadIdx.x;
    const int tx = t & 15, ty = t >> 4;
    const int b = blockIdx.z;
    const int o0 = blockIdx.y * 64;
    const int n0 = blockIdx.x * 64;
    const float* xb = x + (size_t)b * 256 * 4096;

    float acc[4][4];
#pragma unroll
    for (int i = 0; i < 4; i++)
#pragma unroll
        for (int j = 0; j < 4; j++) acc[i][j] = 0.f;

    const int wo = t >> 2, wcg = (t & 3) << 2;
    for (int c0 = 0; c0 < 256; c0 += 16) {
        __syncthreads();
        float4 wv = *(const float4*)(w + (size_t)(o0 + wo) * 256 + c0 + wcg);
        WsT[(wcg + 0) * 68 + wo] = wv.x;
        WsT[(wcg + 1) * 68 + wo] = wv.y;
        WsT[(wcg + 2) * 68 + wo] = wv.z;
        WsT[(wcg + 3) * 68 + wo] = wv.w;
        *(float4*)(Xs + ty * 68 + tx * 4) =
            *(const float4*)(xb + (size_t)(c0 + ty) * 4096 + n0 + tx * 4);
        __syncthreads();
#pragma unroll
        for (int c = 0; c < 16; c++) {
            const float4 a4 = *(const float4*)(WsT + c * 68 + ty * 4);
            const float4 b4 = *(const float4*)(Xs + c * 68 + tx * 4);
            const float av[4] = {a4.x, a4.y, a4.z, a4.w};
            const float bv[4] = {b4.x, b4.y, b4.z, b4.w};
#pragma unroll
            for (int ri = 0; ri < 4; ri++)
#pragma unroll
                for (int cj = 0; cj < 4; cj++) acc[ri][cj] += av[ri] * bv[cj];
        }
    }

    const int nbase = n0 + tx * 4;
    const int by = blockIdx.y;
    if (by < 8) {
        // Q (scaled) or K -> [bh][n][d] fp16
        __half* dst = (by < 4) ? g_q16 : g_k16;
        const float sc = (by < 4) ? SCALE_F : 1.0f;
        const int bh = b * 4 + (by & 3);
        const int d0 = ty * 4;
#pragma unroll
        for (int cj = 0; cj < 4; cj++) {
            __half2* p = (__half2*)(dst + ((size_t)bh * 4096 + nbase + cj) * 64 + d0);
            p[0] = __floats2half2_rn(acc[0][cj] * sc, acc[1][cj] * sc);
            p[1] = __floats2half2_rn(acc[2][cj] * sc, acc[3][cj] * sc);
        }
    } else {
        // V -> [bh][dv][m] fp16
        const int bh = b * 4 + (by - 8);
        const int dv0 = ty * 4;
#pragma unroll
        for (int ri = 0; ri < 4; ri++) {
            __half2* p = (__half2*)(g_v16 + ((size_t)bh * 64 + dv0 + ri) * 4096 + nbase);
            p[0] = __floats2half2_rn(acc[ri][0], acc[ri][1]);
            p[1] = __floats2half2_rn(acc[ri][2], acc[ri][3]);
        }
    }
}

// ---------------------------------------------------------------------------
// Kernel 2: rel-pos logits (reads fp16 q, un-scales by 8, fp32 math)
// ---------------------------------------------------------------------------
__global__ void __launch_bounds__(256) rel_kernel(const float* __restrict__ hrel,
                                                  const float* __restrict__ wrel) {
    __shared__ float qs[64 * 68];     // [d][n], stride 68 (16B-aligned for float4)
    __shared__ float relT[64 * 128];  // [d][r]
    const int t = threadIdx.x;
    const int bh = blockIdx.y;
    const int n0 = blockIdx.x * 64;
    const float* rel = blockIdx.z ? wrel : hrel;
    float* outb = blockIdx.z ? g_qw : g_qh;

    // stage q: [n][d] fp16 rows -> qs[d][n] fp32 (x8 to undo the 0.125)
    {
        const int dg = (t & 7) * 8;
        const int nb = t >> 3;  // 0..31
#pragma unroll
        for (int it = 0; it < 2; it++) {
            int n = nb + it * 32;
            uint4 raw = *(const uint4*)(g_q16 + ((size_t)bh * 4096 + n0 + n) * 64 + dg);
            const __half2* hp = (const __half2*)&raw;
#pragma unroll
            for (int z = 0; z < 4; z++) {
                float2 f = __half22float2(hp[z]);
                qs[(dg + 2 * z + 0) * 68 + n] = f.x * 8.0f;
                qs[(dg + 2 * z + 1) * 68 + n] = f.y * 8.0f;
            }
        }
    }
    {
        int r = t >> 1, half = t & 1;
#pragma unroll
        for (int k = 0; k < 8; k++) {
            int d = half * 32 + k * 4;
            float4 rv = (r < 127) ? *(const float4*)(rel + r * 64 + d)
                                  : make_float4(0.f, 0.f, 0.f, 0.f);
            relT[(d + 0) * 128 + r] = rv.x;
            relT[(d + 1) * 128 + r] = rv.y;
            relT[(d + 2) * 128 + r] = rv.z;
            relT[(d + 3) * 128 + r] = rv.w;
        }
    }
    __syncthreads();

    const int tr = t & 31;
    const int tn = t >> 5;
    float acc[8][4];
#pragma unroll
    for (int i = 0; i < 8; i++)
#pragma unroll
        for (int j = 0; j < 4; j++) acc[i][j] = 0.f;

#pragma unroll 8
    for (int d = 0; d < 64; d++) {
        const float4 b4 = *(const float4*)(relT + d * 128 + tr * 4);
        const float4 a0 = *(const float4*)(qs + d * 68 + tn * 8);
        const float4 a1 = *(const float4*)(qs + d * 68 + tn * 8 + 4);
        const float av[8] = {a0.x, a0.y, a0.z, a0.w, a1.x, a1.y, a1.z, a1.w};
        const float bv[4] = {b4.x, b4.y, b4.z, b4.w};
#pragma unroll
        for (int i = 0; i < 8; i++)
#pragma unroll
            for (int j = 0; j < 4; j++) acc[i][j] += av[i] * bv[j];
    }
#pragma unroll
    for (int i = 0; i < 8; i++) {
        *(float4*)(outb + ((size_t)bh * 4096 + n0 + tn * 8 + i) * 128 + tr * 4) =
            make_float4(acc[i][0], acc[i][1], acc[i][2], acc[i][3]);
    }
}

// ---------------------------------------------------------------------------
// Kernel 3: fp16 flash attention. Br=128, Bc=64, 8 warps, FA-2 register P.
// smem tiles: 128B rows, 16B-chunk swizzle  phys = row*128 + (c*16 ^ (row&7)*16)
// ---------------------------------------------------------------------------
#define FL_SMEM 49152

__global__ void __launch_bounds__(256, 1) flash_kernel(float* __restrict__ out) {
    extern __shared__ __align__(128) char smem[];
    const uint32_t sb = smem_to_u32(smem);
    const uint32_t Qs = sb;  // 16384
    const uint32_t Kbuf0 = sb + 16384, Kbuf1 = sb + 24576;
    const uint32_t Vbuf0 = sb + 32768, Vbuf1 = sb + 40960;

    const int t = threadIdx.x;
    const int w = t >> 5, lane = t & 31;
    const int gid = lane >> 2, tig = lane & 3;
    const int r0 = w * 16;
    const int bh = blockIdx.y, qb = blockIdx.x;
    const int n0q = qb * 128;
    const __half* qg = g_q16 + (size_t)bh * 4096 * 64;
    const __half* kg = g_k16 + (size_t)bh * 4096 * 64;
    const __half* vg = g_v16 + (size_t)bh * 64 * 4096;

    // ---- prologue: cp.async Q + K/V(j=0)
    for (int c = t; c < 1024; c += 256) {
        int row = c >> 3, kc = c & 7;
        cp16(Qs + row * 128 + ((kc * 16) ^ ((row & 7) * 16)),
             qg + (size_t)(n0q + row) * 64 + kc * 8);
    }
    for (int c = t; c < 512; c += 256) {
        int row = c >> 3, kc = c & 7;
        uint32_t sw = (kc * 16) ^ ((row & 7) * 16);
        cp16(Kbuf0 + row * 128 + sw, kg + (size_t)row * 64 + kc * 8);
        cp16(Vbuf0 + row * 128 + sw, vg + (size_t)row * 4096 + kc * 8);
    }
    CP_COMMIT();
    cp_wait<0>();
    __syncthreads();

    // ---- Q fragments (persist all j)
    uint32_t qf[4][4];
    {
        const int qrow = r0 + ((lane >> 3) & 1) * 8 + (lane & 7);
        const uint32_t qx = (lane & 7) * 16;
        const uint32_t qbase = Qs + qrow * 128;
#pragma unroll
        for (int kt = 0; kt < 4; kt++)
            ldm_x4(qf[kt][0], qf[kt][1], qf[kt][2], qf[kt][3],
                   qbase + ((uint32_t)((kt * 2 + (lane >> 4)) * 16) ^ qx));
    }

    // ---- biases
    const int i_lo = r0 + gid, i_hi = i_lo + 8;
    float qwv[8][4];
    {
        const float* qwb = g_qw + ((size_t)bh * 4096 + n0q) * 128;
#pragma unroll
        for (int nt = 0; nt < 8; nt++) {
            int c = nt * 8 + 2 * tig;
            qwv[nt][0] = qwb[(size_t)i_lo * 128 + (c - (i_lo & 63) + 63)];
            qwv[nt][1] = qwb[(size_t)i_lo * 128 + (c + 1 - (i_lo & 63) + 63)];
            qwv[nt][2] = qwb[(size_t)i_hi * 128 + (c - (i_hi & 63) + 63)];
            qwv[nt][3] = qwb[(size_t)i_hi * 128 + (c + 1 - (i_hi & 63) + 63)];
        }
    }
    const float* pqh_lo =
        g_qh + ((size_t)bh * 4096 + n0q + i_lo) * 128 + 63 - (qb * 2 + (i_lo >> 6));
    const float* pqh_hi =
        g_qh + ((size_t)bh * 4096 + n0q + i_hi) * 128 + 63 - (qb * 2 + (i_hi >> 6));

    // per-lane ldmatrix constants (K/V pattern)
    const int kv_row = ((lane >> 4) & 1) * 8 + (lane & 7);
    const int kv_csel = (lane >> 3) & 1;
    const uint32_t kv_x = (lane & 7) * 16;

    float m_lo = -3.0e38f, m_hi = -3.0e38f, l_lo = 0.f, l_hi = 0.f;
    float O[8][4];
#pragma unroll
    for (int nt = 0; nt < 8; nt++)
#pragma unroll
        for (int e = 0; e < 4; e++) O[nt][e] = 0.f;

    for (int j = 0; j < 64; j++) {
        __syncthreads();  // all warps done reading buf^1 (iter j-1)
        if (j + 1 < 64) {
            const uint32_t kb = (j & 1) ? Kbuf0 : Kbuf1;
            const uint32_t vb = (j & 1) ? Vbuf0 : Vbuf1;
            for (int c = t; c < 512; c += 256) {
                int row = c >> 3, kc = c & 7;
                uint32_t sw = (kc * 16) ^ ((row & 7) * 16);
                cp16(kb + row * 128 + sw,
                     kg + ((size_t)(j + 1) * 64 + row) * 64 + kc * 8);
                cp16(vb + row * 128 + sw,
                     vg + (size_t)row * 4096 + (j + 1) * 64 + kc * 8);
            }
            CP_COMMIT();
            cp_wait<1>();
        } else {
            cp_wait<0>();
        }
        __syncthreads();

        const float qh_lo = pqh_lo[j], qh_hi = pqh_hi[j];
        const uint32_t Kb = (j & 1) ? Kbuf1 : Kbuf0;
        const uint32_t Vb = (j & 1) ? Vbuf1 : Vbuf0;

        // ---- S = (scaled Q) K^T
        float S[8][4];
#pragma unroll
        for (int nt = 0; nt < 8; nt++)
#pragma unroll
            for (int e = 0; e < 4; e++) S[nt][e] = 0.f;

#pragma unroll
        for (int kt = 0; kt < 4; kt++) {
#pragma unroll
            for (int ntp = 0; ntp < 4; ntp++) {
                uint32_t b0, b1, b2, b3;
                uint32_t addr = Kb + (uint32_t)(ntp * 16 + kv_row) * 128 +
                                ((uint32_t)((kt * 2 + kv_csel) * 16) ^ kv_x);
                ldm_x4(b0, b1, b2, b3, addr);
                mma_f16(S[2 * ntp], qf[kt][0], qf[kt][1], qf[kt][2], qf[kt][3], b0, b1);
                mma_f16(S[2 * ntp + 1], qf[kt][0], qf[kt][1], qf[kt][2], qf[kt][3], b2, b3);
            }
        }

        // ---- bias + online softmax (rows warp-local across quad lanes)
        float mx_lo = -3.0e38f, mx_hi = -3.0e38f;
#pragma unroll
        for (int nt = 0; nt < 8; nt++) {
            S[nt][0] += qh_lo + qwv[nt][0];
            S[nt][1] += qh_lo + qwv[nt][1];
            S[nt][2] += qh_hi + qwv[nt][2];
            S[nt][3] += qh_hi + qwv[nt][3];
            mx_lo = fmaxf(mx_lo, fmaxf(S[nt][0], S[nt][1]));
            mx_hi = fmaxf(mx_hi, fmaxf(S[nt][2], S[nt][3]));
        }
        mx_lo = fmaxf(mx_lo, __shfl_xor_sync(0xffffffffu, mx_lo, 1));
        mx_lo = fmaxf(mx_lo, __shfl_xor_sync(0xffffffffu, mx_lo, 2));
        mx_hi = fmaxf(mx_hi, __shfl_xor_sync(0xffffffffu, mx_hi, 1));
        mx_hi = fmaxf(mx_hi, __shfl_xor_sync(0xffffffffu, mx_hi, 2));
        const float mnew_lo = fmaxf(m_lo, mx_lo);
        const float mnew_hi = fmaxf(m_hi, mx_hi);
        const float alpha_lo = __expf(m_lo - mnew_lo);
        const float alpha_hi = __expf(m_hi - mnew_hi);
        m_lo = mnew_lo; m_hi = mnew_hi;

        uint32_t ph[8][2];
        float sum_lo = 0.f, sum_hi = 0.f;
#pragma unroll
        for (int nt = 0; nt < 8; nt++) {
            float e0 = __expf(S[nt][0] - mnew_lo);
            float e1 = __expf(S[nt][1] - mnew_lo);
            float e2 = __expf(S[nt][2] - mnew_hi);
            float e3 = __expf(S[nt][3] - mnew_hi);
            sum_lo += e0 + e1;
            sum_hi += e2 + e3;
            ph[nt][0] = packh2(e0, e1);
            ph[nt][1] = packh2(e2, e3);
        }
        sum_lo += __shfl_xor_sync(0xffffffffu, sum_lo, 1);
        sum_lo += __shfl_xor_sync(0xffffffffu, sum_lo, 2);
        sum_hi += __shfl_xor_sync(0xffffffffu, sum_hi, 1);
        sum_hi += __shfl_xor_sync(0xffffffffu, sum_hi, 2);
        l_lo = l_lo * alpha_lo + sum_lo;
        l_hi = l_hi * alpha_hi + sum_hi;
#pragma unroll
        for (int nt = 0; nt < 8; nt++) {
            O[nt][0] *= alpha_lo; O[nt][1] *= alpha_lo;
            O[nt][2] *= alpha_hi; O[nt][3] *= alpha_hi;
        }

        // ---- O += P @ V   (P A-frags straight from registers)
#pragma unroll
        for (int kt = 0; kt < 4; kt++) {
            const uint32_t pa0 = ph[2 * kt][0], pa1 = ph[2 * kt][1];
            const uint32_t pa2 = ph[2 * kt + 1][0], pa3 = ph[2 * kt + 1][1];
#pragma unroll
            for (int ntp = 0; ntp < 4; ntp++) {
                uint32_t b0, b1, b2, b3;
                uint32_t addr = Vb + (uint32_t)(ntp * 16 + kv_row) * 128 +
                                ((uint32_t)((kt * 2 + kv_csel) * 16) ^ kv_x);
                ldm_x4(b0, b1, b2, b3, addr);
                mma_f16(O[2 * ntp], pa0, pa1, pa2, pa3, b0, b1);
                mma_f16(O[2 * ntp + 1], pa0, pa1, pa2, pa3, b2, b3);
            }
        }
    }

    // ---- epilogue: normalize, transpose via smem [dv][i] stride 132, store
    __syncthreads();
    const float inv_lo = 1.0f / l_lo, inv_hi = 1.0f / l_hi;
    float* Os = (float*)smem;
#pragma unroll
    for (int nt = 0; nt < 8; nt++) {
        int dv = nt * 8 + 2 * tig;
        Os[(dv + 0) * 132 + i_lo] = O[nt][0] * inv_lo;
        Os[(dv + 1) * 132 + i_lo] = O[nt][1] * inv_lo;
        Os[(dv + 0) * 132 + i_hi] = O[nt][2] * inv_hi;
        Os[(dv + 1) * 132 + i_hi] = O[nt][3] * inv_hi;
    }
    __syncthreads();

    const int b = bh >> 2, head = bh & 3;
    float* outp = out + ((size_t)(b * 256 + head * 64)) * 4096 + n0q;
    for (int idx = t * 4; idx < 8192; idx += 1024) {
        int dv = idx >> 7, i = idx & 127;
        *(float4*)(outp + (size_t)dv * 4096 + i) = *(const float4*)(Os + dv * 132 + i);
    }
}

// ---------------------------------------------------------------------------
extern "C" void kernel_launch(void* const* d_in, const int* in_sizes, int n_in,
                              void* d_out, int out_size) {
    const float* x = (const float*)d_in[0];
    const float* w = (const float*)d_in[1];
    const float* hrel = (const float*)d_in[2];
    const float* wrel = (const float*)d_in[3];
    float* out = (float*)d_out;

    qkv_kernel<<<dim3(64, 12, 2), 256>>>(x, w);
    rel_kernel<<<dim3(64, 8, 2), 256>>>(hrel, wrel);

    cudaFuncSetAttribute(flash_kernel, cudaFuncAttributeMaxDynamicSharedMemorySize,
                         FL_SMEM);
    flash_kernel<<<dim3(32, 8), 256, FL_SMEM>>>(out);
}

// round 6
// speedup vs baseline: 5.9833x; 1.4692x over previous
#include <cuda_runtime.h>
#include <cuda_fp16.h>
#include <cstdint>
#include <cstddef>

#define SCALE_F 0.125f

__device__ __forceinline__ uint32_t smem_to_u32(const void* p) {
    uint32_t a;
    asm("{ .reg .u64 t; cvta.to.shared.u64 t, %1; cvt.u32.u64 %0, t; }" : "=r"(a) : "l"(p));
    return a;
}
__device__ __forceinline__ void cp16(uint32_t dst, const void* src) {
    asm volatile("cp.async.cg.shared.global [%0], [%1], 16;" :: "r"(dst), "l"(src) : "memory");
}
#define CP_COMMIT() asm volatile("cp.async.commit_group;" ::: "memory")
template <int N>
__device__ __forceinline__ void cp_wait() {
    asm volatile("cp.async.wait_group %0;" :: "n"(N) : "memory");
}
__device__ __forceinline__ void ldm_x4(uint32_t& r0, uint32_t& r1, uint32_t& r2,
                                       uint32_t& r3, uint32_t addr) {
    asm volatile("ldmatrix.sync.aligned.m8n8.x4.shared.b16 {%0,%1,%2,%3}, [%4];"
                 : "=r"(r0), "=r"(r1), "=r"(r2), "=r"(r3) : "r"(addr));
}
__device__ __forceinline__ void ldm_x4t(uint32_t& r0, uint32_t& r1, uint32_t& r2,
                                        uint32_t& r3, uint32_t addr) {
    asm volatile("ldmatrix.sync.aligned.m8n8.x4.trans.shared.b16 {%0,%1,%2,%3}, [%4];"
                 : "=r"(r0), "=r"(r1), "=r"(r2), "=r"(r3) : "r"(addr));
}
__device__ __forceinline__ void mma_f16(float c[4], uint32_t a0, uint32_t a1,
                                        uint32_t a2, uint32_t a3, uint32_t b0,
                                        uint32_t b1) {
    asm volatile(
        "mma.sync.aligned.m16n8k16.row.col.f32.f16.f16.f32 "
        "{%0,%1,%2,%3},{%4,%5,%6,%7},{%8,%9},{%0,%1,%2,%3};\n"
        : "+f"(c[0]), "+f"(c[1]), "+f"(c[2]), "+f"(c[3])
        : "r"(a0), "r"(a1), "r"(a2), "r"(a3), "r"(b0), "r"(b1));
}
__device__ __forceinline__ uint32_t packh2(float lo, float hi) {
    __half2 h = __floats2half2_rn(lo, hi);
    return *(uint32_t*)&h;
}

// ===================== scratch =====================
__device__ __align__(16) __half g_x16[2 * 256 * 4096];     // [b][c][n]
__device__ __align__(16) __half g_w16[768 * 256];          // [o][c]
__device__ __align__(16) __half g_q16[2 * 4 * 4096 * 64];  // [bh][n][d], pre-scaled x0.125
__device__ __align__(16) __half g_k16[2 * 4 * 4096 * 64];  // [bh][n][d]
__device__ __align__(16) __half g_v16[2 * 4 * 64 * 4096];  // [bh][dv][m]
__device__ float g_qh[8 * 4096 * 128];                     // [bh][n][r]
__device__ float g_qw[8 * 4096 * 128];

// ---------------------------------------------------------------------------
// Kernel 0: fp32 -> fp16 conversion for x and w
// ---------------------------------------------------------------------------
#define X_F4 524288   // 2*256*4096 / 4
#define W_F4 49152    // 768*256 / 4
__global__ void __launch_bounds__(256) cvt_kernel(const float* __restrict__ x,
                                                  const float* __restrict__ w) {
    const int idx = blockIdx.x * 256 + threadIdx.x;
    if (idx < X_F4) {
        float4 v = ((const float4*)x)[idx];
        __half2* o = (__half2*)g_x16 + idx * 2;
        o[0] = __floats2half2_rn(v.x, v.y);
        o[1] = __floats2half2_rn(v.z, v.w);
    } else if (idx < X_F4 + W_F4) {
        float4 v = ((const float4*)w)[idx - X_F4];
        __half2* o = (__half2*)g_w16 + (idx - X_F4) * 2;
        o[0] = __floats2half2_rn(v.x, v.y);
        o[1] = __floats2half2_rn(v.z, v.w);
    }
}

// ---------------------------------------------------------------------------
// Kernel 1: QKV projection, fp16 tensor-core GEMM.
// C[o][n] = sum_c w16[o][c] * x16[b][c][n].  CTA tile 128(o) x 128(n), K=256.
// grid (32 n-tiles, 6 o-tiles, 2 b), 8 warps as 4(o) x 2(n).
// Epilogue: ot 0-3 (q,k) -> transpose to [n][d]; ot 4-5 (v) -> natural [dv][n].
// ---------------------------------------------------------------------------
__global__ void __launch_bounds__(256, 1) qkv_mma_kernel() {
    extern __shared__ __align__(128) char smem[];
    const uint32_t sb = smem_to_u32(smem);
    const int t = threadIdx.x;
    const int w = t >> 5, lane = t & 31;
    const int gid = lane >> 2, tig = lane & 3;
    const int wo = w >> 1, wn = w & 1;
    const int n0 = blockIdx.x * 128;
    const int ot = blockIdx.y;
    const int b = blockIdx.z;

    const __half* wg = g_w16 + (size_t)ot * 128 * 256;
    const __half* xg = g_x16 + (size_t)b * 256 * 4096 + n0;

    // stage s: A at s*32768 (128 x 128B), B at s*32768+16384 (64 x 256B)
    auto load_stage = [&](int kc, int s) {
        const uint32_t As = sb + s * 32768;
        const uint32_t Bs = As + 16384;
        for (int idx = t; idx < 1024; idx += 256) {
            int row = idx >> 3, ch = idx & 7;
            cp16(As + row * 128 + ((ch ^ (row & 7)) * 16),
                 wg + (size_t)row * 256 + kc * 64 + ch * 8);
        }
        for (int idx = t; idx < 1024; idx += 256) {
            int row = idx >> 4, ch = idx & 15;
            cp16(Bs + row * 256 + ((ch ^ (row & 7)) * 16),
                 xg + (size_t)(kc * 64 + row) * 4096 + ch * 8);
        }
        CP_COMMIT();
    };

    float C[2][8][4];
#pragma unroll
    for (int mt = 0; mt < 2; mt++)
#pragma unroll
        for (int ng = 0; ng < 8; ng++)
#pragma unroll
            for (int e = 0; e < 4; e++) C[mt][ng][e] = 0.f;

    load_stage(0, 0);

    // per-lane ldmatrix constants
    const int a_rlane = ((lane >> 3) & 1) * 8 + (lane & 7);  // row within 16
    const uint32_t a_x = (lane & 7) * 16;
    const int b_row = lane & 15;
    const int b_cg = lane >> 4;  // n 8-group within 16

    for (int kc = 0; kc < 4; kc++) {
        if (kc + 1 < 4) {
            load_stage(kc + 1, (kc + 1) & 1);
            cp_wait<1>();
        } else {
            cp_wait<0>();
        }
        __syncthreads();
        const uint32_t As = sb + (kc & 1) * 32768;
        const uint32_t Bs = As + 16384;

#pragma unroll
        for (int ks = 0; ks < 4; ks++) {
            // A frags: 2 m-tiles
            uint32_t af[2][4];
#pragma unroll
            for (int mt = 0; mt < 2; mt++) {
                int arow = wo * 32 + mt * 16 + a_rlane;
                ldm_x4(af[mt][0], af[mt][1], af[mt][2], af[mt][3],
                       As + arow * 128 + (((uint32_t)((ks * 2 + (lane >> 4)) * 16)) ^ a_x));
            }
            // B frags: 4 n-16-groups (trans)
#pragma unroll
            for (int ng2 = 0; ng2 < 4; ng2++) {
                uint32_t b0, b1, b2, b3;
                int brow = ks * 16 + b_row;
                int bch = wn * 8 + ng2 * 2 + b_cg;
                ldm_x4t(b0, b1, b2, b3,
                        Bs + brow * 256 + ((bch ^ (brow & 7)) * 16));
#pragma unroll
                for (int mt = 0; mt < 2; mt++) {
                    mma_f16(C[mt][2 * ng2], af[mt][0], af[mt][1], af[mt][2], af[mt][3], b0, b1);
                    mma_f16(C[mt][2 * ng2 + 1], af[mt][0], af[mt][1], af[mt][2], af[mt][3], b2, b3);
                }
            }
        }
        __syncthreads();
    }

    // ---------------- epilogue ----------------
    const float sc = (ot < 2) ? SCALE_F : 1.0f;
    __half* Cs = (__half*)smem;  // stride 136 halfs
    if (ot < 4) {
        // transpose: Cs_t[n][lo]
#pragma unroll
        for (int mt = 0; mt < 2; mt++) {
            const int r_lo = wo * 32 + mt * 16 + gid, r_hi = r_lo + 8;
#pragma unroll
            for (int ng = 0; ng < 8; ng++) {
                const int c = wn * 64 + ng * 8 + 2 * tig;
                Cs[(c + 0) * 136 + r_lo] = __float2half_rn(C[mt][ng][0] * sc);
                Cs[(c + 1) * 136 + r_lo] = __float2half_rn(C[mt][ng][1] * sc);
                Cs[(c + 0) * 136 + r_hi] = __float2half_rn(C[mt][ng][2] * sc);
                Cs[(c + 1) * 136 + r_hi] = __float2half_rn(C[mt][ng][3] * sc);
            }
        }
        __syncthreads();
        __half* dst = (ot < 2) ? g_q16 : g_k16;
        const int otq = (ot < 2) ? ot : (ot - 2);
        for (int idx = t; idx < 2048; idx += 256) {
            int n = idx >> 4, hs = (idx >> 3) & 1, ch = idx & 7;
            int bh = b * 4 + otq * 2 + hs;
            *(uint4*)(dst + ((size_t)bh * 4096 + n0 + n) * 64 + ch * 8) =
                *(const uint4*)(Cs + n * 136 + hs * 64 + ch * 8);
        }
    } else {
        // natural: Cs[lo][n]
#pragma unroll
        for (int mt = 0; mt < 2; mt++) {
            const int r_lo = wo * 32 + mt * 16 + gid, r_hi = r_lo + 8;
#pragma unroll
            for (int ng = 0; ng < 8; ng++) {
                const int c = wn * 64 + ng * 8 + 2 * tig;
                *(__half2*)(Cs + r_lo * 136 + c) = __floats2half2_rn(C[mt][ng][0], C[mt][ng][1]);
                *(__half2*)(Cs + r_hi * 136 + c) = __floats2half2_rn(C[mt][ng][2], C[mt][ng][3]);
            }
        }
        __syncthreads();
        const int otv = ot - 4;
        for (int idx = t; idx < 2048; idx += 256) {
            int lo = idx >> 4, ch = idx & 15;
            int bh = b * 4 + otv * 2 + (lo >> 6);
            int dv = lo & 63;
            *(uint4*)(g_v16 + ((size_t)bh * 64 + dv) * 4096 + n0 + ch * 8) =
                *(const uint4*)(Cs + lo * 136 + ch * 8);
        }
    }
}

// ---------------------------------------------------------------------------
// Kernel 2: rel-pos logits, fp16 mma.  S[n][r] = q[n][.] . rel[r][.]
// CTA: 128 n x 128 r, K=64. grid (32, 8 bh, 2 type). Same frag patterns as flash.
// ---------------------------------------------------------------------------
__global__ void __launch_bounds__(256) rel_mma_kernel(const float* __restrict__ hrel,
                                                      const float* __restrict__ wrel) {
    __shared__ __align__(128) char smem_r[32768];
    const uint32_t sb = smem_to_u32(smem_r);
    const uint32_t Qs = sb;            // 128 rows x 128 B
    const uint32_t Rs = sb + 16384;    // 128 rows x 128 B
    const int t = threadIdx.x;
    const int w = t >> 5, lane = t & 31;
    const int gid = lane >> 2, tig = lane & 3;
    const int bh = blockIdx.y;
    const int n0 = blockIdx.x * 128;
    const float* rel = blockIdx.z ? wrel : hrel;
    float* outb = blockIdx.z ? g_qw : g_qh;

    // stage Q via cp.async
    for (int idx = t; idx < 1024; idx += 256) {
        int row = idx >> 3, ch = idx & 7;
        cp16(Qs + row * 128 + ((ch ^ (row & 7)) * 16),
             g_q16 + ((size_t)bh * 4096 + n0 + row) * 64 + ch * 8);
    }
    CP_COMMIT();
    // stage rel (fp32 -> fp16, x8 to undo Q pre-scale; row 127 = 0)
    for (int idx = t; idx < 1024; idx += 256) {
        int r = idx >> 3, ch = idx & 7;
        __half2 h[4];
        if (r < 127) {
            float4 v0 = *(const float4*)(rel + r * 64 + ch * 8);
            float4 v1 = *(const float4*)(rel + r * 64 + ch * 8 + 4);
            h[0] = __floats2half2_rn(v0.x * 8.f, v0.y * 8.f);
            h[1] = __floats2half2_rn(v0.z * 8.f, v0.w * 8.f);
            h[2] = __floats2half2_rn(v1.x * 8.f, v1.y * 8.f);
            h[3] = __floats2half2_rn(v1.z * 8.f, v1.w * 8.f);
        } else {
            h[0] = h[1] = h[2] = h[3] = __floats2half2_rn(0.f, 0.f);
        }
        *(uint4*)((char*)smem_r + 16384 + r * 128 + ((ch ^ (r & 7)) * 16)) = *(uint4*)h;
    }
    cp_wait<0>();
    __syncthreads();

    // Q A-frags (warp owns rows w*16..+15)
    const int r0 = w * 16;
    uint32_t qf[4][4];
    {
        const int qrow = r0 + ((lane >> 3) & 1) * 8 + (lane & 7);
        const uint32_t qx = (lane & 7) * 16;
#pragma unroll
        for (int kt = 0; kt < 4; kt++)
            ldm_x4(qf[kt][0], qf[kt][1], qf[kt][2], qf[kt][3],
                   Qs + qrow * 128 + (((uint32_t)((kt * 2 + (lane >> 4)) * 16)) ^ qx));
    }

    const int kv_row = ((lane >> 4) & 1) * 8 + (lane & 7);
    const int kv_csel = (lane >> 3) & 1;
    const uint32_t kv_x = (lane & 7) * 16;

    float S[16][4];
#pragma unroll
    for (int nt = 0; nt < 16; nt++)
#pragma unroll
        for (int e = 0; e < 4; e++) S[nt][e] = 0.f;

#pragma unroll
    for (int kt = 0; kt < 4; kt++) {
#pragma unroll
        for (int ntp = 0; ntp < 8; ntp++) {
            uint32_t b0, b1, b2, b3;
            ldm_x4(b0, b1, b2, b3,
                   Rs + (uint32_t)(ntp * 16 + kv_row) * 128 +
                       (((uint32_t)((kt * 2 + kv_csel) * 16)) ^ kv_x));
            mma_f16(S[2 * ntp], qf[kt][0], qf[kt][1], qf[kt][2], qf[kt][3], b0, b1);
            mma_f16(S[2 * ntp + 1], qf[kt][0], qf[kt][1], qf[kt][2], qf[kt][3], b2, b3);
        }
    }

    const int i_lo = r0 + gid, i_hi = i_lo + 8;
#pragma unroll
    for (int nt = 0; nt < 16; nt++) {
        const int c = nt * 8 + 2 * tig;
        *(float2*)(outb + ((size_t)bh * 4096 + n0 + i_lo) * 128 + c) =
            make_float2(S[nt][0], S[nt][1]);
        *(float2*)(outb + ((size_t)bh * 4096 + n0 + i_hi) * 128 + c) =
            make_float2(S[nt][2], S[nt][3]);
    }
}

// ---------------------------------------------------------------------------
// Kernel 3: fp16 flash attention (unchanged from R5).
// ---------------------------------------------------------------------------
#define FL_SMEM 49152

__global__ void __launch_bounds__(256, 1) flash_kernel(float* __restrict__ out) {
    extern __shared__ __align__(128) char smem[];
    const uint32_t sb = smem_to_u32(smem);
    const uint32_t Qs = sb;  // 16384
    const uint32_t Kbuf0 = sb + 16384, Kbuf1 = sb + 24576;
    const uint32_t Vbuf0 = sb + 32768, Vbuf1 = sb + 40960;

    const int t = threadIdx.x;
    const int w = t >> 5, lane = t & 31;
    const int gid = lane >> 2, tig = lane & 3;
    const int r0 = w * 16;
    const int bh = blockIdx.y, qb = blockIdx.x;
    const int n0q = qb * 128;
    const __half* qg = g_q16 + (size_t)bh * 4096 * 64;
    const __half* kg = g_k16 + (size_t)bh * 4096 * 64;
    const __half* vg = g_v16 + (size_t)bh * 64 * 4096;

    for (int c = t; c < 1024; c += 256) {
        int row = c >> 3, kc = c & 7;
        cp16(Qs + row * 128 + ((kc * 16) ^ ((row & 7) * 16)),
             qg + (size_t)(n0q + row) * 64 + kc * 8);
    }
    for (int c = t; c < 512; c += 256) {
        int row = c >> 3, kc = c & 7;
        uint32_t sw = (kc * 16) ^ ((row & 7) * 16);
        cp16(Kbuf0 + row * 128 + sw, kg + (size_t)row * 64 + kc * 8);
        cp16(Vbuf0 + row * 128 + sw, vg + (size_t)row * 4096 + kc * 8);
    }
    CP_COMMIT();
    cp_wait<0>();
    __syncthreads();

    uint32_t qf[4][4];
    {
        const int qrow = r0 + ((lane >> 3) & 1) * 8 + (lane & 7);
        const uint32_t qx = (lane & 7) * 16;
        const uint32_t qbase = Qs + qrow * 128;
#pragma unroll
        for (int kt = 0; kt < 4; kt++)
            ldm_x4(qf[kt][0], qf[kt][1], qf[kt][2], qf[kt][3],
                   qbase + ((uint32_t)((kt * 2 + (lane >> 4)) * 16) ^ qx));
    }

    const int i_lo = r0 + gid, i_hi = i_lo + 8;
    float qwv[8][4];
    {
        const float* qwb = g_qw + ((size_t)bh * 4096 + n0q) * 128;
#pragma unroll
        for (int nt = 0; nt < 8; nt++) {
            int c = nt * 8 + 2 * tig;
            qwv[nt][0] = qwb[(size_t)i_lo * 128 + (c - (i_lo & 63) + 63)];
            qwv[nt][1] = qwb[(size_t)i_lo * 128 + (c + 1 - (i_lo & 63) + 63)];
            qwv[nt][2] = qwb[(size_t)i_hi * 128 + (c - (i_hi & 63) + 63)];
            qwv[nt][3] = qwb[(size_t)i_hi * 128 + (c + 1 - (i_hi & 63) + 63)];
        }
    }
    const float* pqh_lo =
        g_qh + ((size_t)bh * 4096 + n0q + i_lo) * 128 + 63 - (qb * 2 + (i_lo >> 6));
    const float* pqh_hi =
        g_qh + ((size_t)bh * 4096 + n0q + i_hi) * 128 + 63 - (qb * 2 + (i_hi >> 6));

    const int kv_row = ((lane >> 4) & 1) * 8 + (lane & 7);
    const int kv_csel = (lane >> 3) & 1;
    const uint32_t kv_x = (lane & 7) * 16;

    float m_lo = -3.0e38f, m_hi = -3.0e38f, l_lo = 0.f, l_hi = 0.f;
    float O[8][4];
#pragma unroll
    for (int nt = 0; nt < 8; nt++)
#pragma unroll
        for (int e = 0; e < 4; e++) O[nt][e] = 0.f;

    for (int j = 0; j < 64; j++) {
        __syncthreads();
        if (j + 1 < 64) {
            const uint32_t kb = (j & 1) ? Kbuf0 : Kbuf1;
            const uint32_t vb = (j & 1) ? Vbuf0 : Vbuf1;
            for (int c = t; c < 512; c += 256) {
                int row = c >> 3, kc = c & 7;
                uint32_t sw = (kc * 16) ^ ((row & 7) * 16);
                cp16(kb + row * 128 + sw,
                     kg + ((size_t)(j + 1) * 64 + row) * 64 + kc * 8);
                cp16(vb + row * 128 + sw,
                     vg + (size_t)row * 4096 + (j + 1) * 64 + kc * 8);
            }
            CP_COMMIT();
            cp_wait<1>();
        } else {
            cp_wait<0>();
        }
        __syncthreads();

        const float qh_lo = pqh_lo[j], qh_hi = pqh_hi[j];
        const uint32_t Kb = (j & 1) ? Kbuf1 : Kbuf0;
        const uint32_t Vb = (j & 1) ? Vbuf1 : Vbuf0;

        float S[8][4];
#pragma unroll
        for (int nt = 0; nt < 8; nt++)
#pragma unroll
            for (int e = 0; e < 4; e++) S[nt][e] = 0.f;

#pragma unroll
        for (int kt = 0; kt < 4; kt++) {
#pragma unroll
            for (int ntp = 0; ntp < 4; ntp++) {
                uint32_t b0, b1, b2, b3;
                uint32_t addr = Kb + (uint32_t)(ntp * 16 + kv_row) * 128 +
                                ((uint32_t)((kt * 2 + kv_csel) * 16) ^ kv_x);
                ldm_x4(b0, b1, b2, b3, addr);
                mma_f16(S[2 * ntp], qf[kt][0], qf[kt][1], qf[kt][2], qf[kt][3], b0, b1);
                mma_f16(S[2 * ntp + 1], qf[kt][0], qf[kt][1], qf[kt][2], qf[kt][3], b2, b3);
            }
        }

        float mx_lo = -3.0e38f, mx_hi = -3.0e38f;
#pragma unroll
        for (int nt = 0; nt < 8; nt++) {
            S[nt][0] += qh_lo + qwv[nt][0];
            S[nt][1] += qh_lo + qwv[nt][1];
            S[nt][2] += qh_hi + qwv[nt][2];
            S[nt][3] += qh_hi + qwv[nt][3];
            mx_lo = fmaxf(mx_lo, fmaxf(S[nt][0], S[nt][1]));
            mx_hi = fmaxf(mx_hi, fmaxf(S[nt][2], S[nt][3]));
        }
        mx_lo = fmaxf(mx_lo, __shfl_xor_sync(0xffffffffu, mx_lo, 1));
        mx_lo = fmaxf(mx_lo, __shfl_xor_sync(0xffffffffu, mx_lo, 2));
        mx_hi = fmaxf(mx_hi, __shfl_xor_sync(0xffffffffu, mx_hi, 1));
        mx_hi = fmaxf(mx_hi, __shfl_xor_sync(0xffffffffu, mx_hi, 2));
        const float mnew_lo = fmaxf(m_lo, mx_lo);
        const float mnew_hi = fmaxf(m_hi, mx_hi);
        const float alpha_lo = __expf(m_lo - mnew_lo);
        const float alpha_hi = __expf(m_hi - mnew_hi);
        m_lo = mnew_lo; m_hi = mnew_hi;

        uint32_t ph[8][2];
        float sum_lo = 0.f, sum_hi = 0.f;
#pragma unroll
        for (int nt = 0; nt < 8; nt++) {
            float e0 = __expf(S[nt][0] - mnew_lo);
            float e1 = __expf(S[nt][1] - mnew_lo);
            float e2 = __expf(S[nt][2] - mnew_hi);
            float e3 = __expf(S[nt][3] - mnew_hi);
            sum_lo += e0 + e1;
            sum_hi += e2 + e3;
            ph[nt][0] = packh2(e0, e1);
            ph[nt][1] = packh2(e2, e3);
        }
        sum_lo += __shfl_xor_sync(0xffffffffu, sum_lo, 1);
        sum_lo += __shfl_xor_sync(0xffffffffu, sum_lo, 2);
        sum_hi += __shfl_xor_sync(0xffffffffu, sum_hi, 1);
        sum_hi += __shfl_xor_sync(0xffffffffu, sum_hi, 2);
        l_lo = l_lo * alpha_lo + sum_lo;
        l_hi = l_hi * alpha_hi + sum_hi;
#pragma unroll
        for (int nt = 0; nt < 8; nt++) {
            O[nt][0] *= alpha_lo; O[nt][1] *= alpha_lo;
            O[nt][2] *= alpha_hi; O[nt][3] *= alpha_hi;
        }

#pragma unroll
        for (int kt = 0; kt < 4; kt++) {
            const uint32_t pa0 = ph[2 * kt][0], pa1 = ph[2 * kt][1];
            const uint32_t pa2 = ph[2 * kt + 1][0], pa3 = ph[2 * kt + 1][1];
#pragma unroll
            for (int ntp = 0; ntp < 4; ntp++) {
                uint32_t b0, b1, b2, b3;
                uint32_t addr = Vb + (uint32_t)(ntp * 16 + kv_row) * 128 +
                                ((uint32_t)((kt * 2 + kv_csel) * 16) ^ kv_x);
                ldm_x4(b0, b1, b2, b3, addr);
                mma_f16(O[2 * ntp], pa0, pa1, pa2, pa3, b0, b1);
                mma_f16(O[2 * ntp + 1], pa0, pa1, pa2, pa3, b2, b3);
            }
        }
    }

    __syncthreads();
    const float inv_lo = 1.0f / l_lo, inv_hi = 1.0f / l_hi;
    float* Os = (float*)smem;
#pragma unroll
    for (int nt = 0; nt < 8; nt++) {
        int dv = nt * 8 + 2 * tig;
        Os[(dv + 0) * 132 + i_lo] = O[nt][0] * inv_lo;
        Os[(dv + 1) * 132 + i_lo] = O[nt][1] * inv_lo;
        Os[(dv + 0) * 132 + i_hi] = O[nt][2] * inv_hi;
        Os[(dv + 1) * 132 + i_hi] = O[nt][3] * inv_hi;
    }
    __syncthreads();

    const int b = bh >> 2, head = bh & 3;
    float* outp = out + ((size_t)(b * 256 + head * 64)) * 4096 + n0q;
    for (int idx = t * 4; idx < 8192; idx += 1024) {
        int dv = idx >> 7, i = idx & 127;
        *(float4*)(outp + (size_t)dv * 4096 + i) = *(const float4*)(Os + dv * 132 + i);
    }
}

// ---------------------------------------------------------------------------
extern "C" void kernel_launch(void* const* d_in, const int* in_sizes, int n_in,
                              void* d_out, int out_size) {
    const float* x = (const float*)d_in[0];
    const float* w = (const float*)d_in[1];
    const float* hrel = (const float*)d_in[2];
    const float* wrel = (const float*)d_in[3];
    float* out = (float*)d_out;

    cvt_kernel<<<(X_F4 + W_F4 + 255) / 256, 256>>>(x, w);

    cudaFuncSetAttribute(qkv_mma_kernel, cudaFuncAttributeMaxDynamicSharedMemorySize,
                         65536);
    qkv_mma_kernel<<<dim3(32, 6, 2), 256, 65536>>>();

    rel_mma_kernel<<<dim3(32, 8, 2), 256>>>(hrel, wrel);

    cudaFuncSetAttribute(flash_kernel, cudaFuncAttributeMaxDynamicSharedMemorySize,
                         FL_SMEM);
    flash_kernel<<<dim3(32, 8), 256, FL_SMEM>>>(out);
}